// round 1
// baseline (speedup 1.0000x reference)
#include <cuda_runtime.h>

// Problem constants
#define BQ 4          // batch
#define NP 16384      // points
#define NQ 4096       // queries (npoint)
#define CF 64         // feature channels
#define KS 32         // nsample
#define OUTC (CF + 3) // 67 output channels

// Stage-1 tiling
#define TPARTS 4
#define PART (NP / TPARTS)   // 4096 points per partial scan
#define CHUNK 2048           // shared-memory tile of points
#define BLK 128              // threads per block (one query per thread)
#define BUFCAP 16            // per-lane candidate buffer depth

// Scratch: partial top-32 per (b, q, part). 2M floats + 2M ints = 16 MB.
__device__ float g_pd[(size_t)BQ * NQ * TPARTS * KS];
__device__ int   g_pi[(size_t)BQ * NQ * TPARTS * KS];

// Sorted-ascending insert into register-resident (dist, idx) arrays.
// Strict '<' everywhere => stable w.r.t. arrival order => ties keep the
// lower point index first (points are scanned in ascending index order),
// matching jax.lax.top_k's stable tie-breaking.
__device__ __forceinline__ void bubble_insert(float (&bd)[KS], int (&bi)[KS],
                                              float d, int i) {
    if (d < bd[KS - 1]) {
        bd[KS - 1] = d;
        bi[KS - 1] = i;
#pragma unroll
        for (int k = KS - 1; k > 0; --k) {
            if (bd[k] < bd[k - 1]) {
                float td = bd[k]; bd[k] = bd[k - 1]; bd[k - 1] = td;
                int   ti = bi[k]; bi[k] = bi[k - 1]; bi[k - 1] = ti;
            } else {
                break;
            }
        }
    }
}

// ---------------------------------------------------------------------------
// Kernel 1: partial exact top-32 over a 4096-point slice of N, per query.
// Grid: (NQ/BLK, TPARTS, BQ). One query per thread.
// Hot loop is distance + compare + (rare) buffered push + warp vote.
// Drains are warp-synchronized so all 32 lanes bubble-insert in parallel.
// ---------------------------------------------------------------------------
__global__ __launch_bounds__(BLK, 4)
void knn_part_kernel(const float* __restrict__ xyz,
                     const float* __restrict__ new_xyz) {
    const int b   = blockIdx.z;
    const int t   = blockIdx.y;
    const int q   = blockIdx.x * BLK + threadIdx.x;
    const int tid = threadIdx.x;

    const float* qp = new_xyz + ((size_t)b * NQ + q) * 3;
    const float qx = qp[0], qy = qp[1], qz = qp[2];

    float bd[KS];
    int   bi[KS];
#pragma unroll
    for (int k = 0; k < KS; k++) {
        bd[k] = __int_as_float(0x7f800000); // +inf
        bi[k] = 0;
    }

    __shared__ float sx[CHUNK], sy[CHUNK], sz[CHUNK];
    __shared__ float sbufd[BLK * BUFCAP];
    __shared__ int   sbufi[BLK * BUFCAP];

    int cnt = 0;
    const int base = t * PART;

    for (int c0 = 0; c0 < PART; c0 += CHUNK) {
        __syncthreads();  // protect tile from overwrite while other warps read
        for (int j = tid; j < CHUNK; j += BLK) {
            const float* p = xyz + ((size_t)b * NP + base + c0 + j) * 3;
            sx[j] = p[0];
            sy[j] = p[1];
            sz[j] = p[2];
        }
        __syncthreads();

        for (int j = 0; j < CHUNK; j++) {
            const float dx = qx - sx[j];
            const float dy = qy - sy[j];
            const float dz = qz - sz[j];
            const float d  = fmaf(dx, dx, fmaf(dy, dy, dz * dz));
            if (d < bd[KS - 1]) {
                sbufd[tid * BUFCAP + cnt] = d;
                sbufi[tid * BUFCAP + cnt] = base + c0 + j;
                cnt++;
            }
            if (__any_sync(0xffffffffu, cnt == BUFCAP)) {
                for (int u = 0; u < cnt; u++) {
                    bubble_insert(bd, bi, sbufd[tid * BUFCAP + u],
                                  sbufi[tid * BUFCAP + u]);
                }
                cnt = 0;
            }
        }
    }
    // Final drain
    for (int u = 0; u < cnt; u++) {
        bubble_insert(bd, bi, sbufd[tid * BUFCAP + u], sbufi[tid * BUFCAP + u]);
    }

    const size_t o = (((size_t)b * NQ + q) * TPARTS + t) * KS;
#pragma unroll
    for (int k = 0; k < KS; k++) {
        g_pd[o + k] = bd[k];
        g_pi[o + k] = bi[k];
    }
}

// ---------------------------------------------------------------------------
// Kernel 2: exact 4-way merge of sorted partial lists -> global top-32,
// fused with the gather / center / transpose / concat epilogue.
// Grid: (NQ, BQ), 128 threads (4 warps). Warp w writes channels w, w+4, ...
// Output layout: out[b][c][p][s], c in [0,67): 0..2 = centered xyz, 3.. = feat.
// ---------------------------------------------------------------------------
__global__ __launch_bounds__(128)
void merge_group_kernel(const float* __restrict__ xyz,
                        const float* __restrict__ new_xyz,
                        const float* __restrict__ feat,
                        float* __restrict__ out) {
    const int p   = blockIdx.x;
    const int b   = blockIdx.y;
    const int tid = threadIdx.x;

    __shared__ float sd[TPARTS * KS];
    __shared__ int   si[TPARTS * KS];
    __shared__ int   sidx[KS];

    const size_t cbase = (((size_t)b * NQ + p) * TPARTS) * KS;
    if (tid < TPARTS * KS) {
        sd[tid] = g_pd[cbase + tid];
        si[tid] = g_pi[cbase + tid];
    }
    __syncthreads();

    if (tid == 0) {
        int p0 = 0, p1 = 0, p2 = 0, p3 = 0;
        for (int k = 0; k < KS; k++) {
            float d0 = sd[0 * KS + p0]; int i0 = si[0 * KS + p0];
            float d1 = sd[1 * KS + p1]; int i1 = si[1 * KS + p1];
            float d2 = sd[2 * KS + p2]; int i2 = si[2 * KS + p2];
            float d3 = sd[3 * KS + p3]; int i3 = si[3 * KS + p3];
            float bdv = d0; int biv = i0; int sel = 0;
            if (d1 < bdv || (d1 == bdv && i1 < biv)) { bdv = d1; biv = i1; sel = 1; }
            if (d2 < bdv || (d2 == bdv && i2 < biv)) { bdv = d2; biv = i2; sel = 2; }
            if (d3 < bdv || (d3 == bdv && i3 < biv)) { bdv = d3; biv = i3; sel = 3; }
            sidx[k] = biv;
            if      (sel == 0) p0++;
            else if (sel == 1) p1++;
            else if (sel == 2) p2++;
            else               p3++;
        }
    }
    __syncthreads();

    const int w    = tid >> 5;
    const int lane = tid & 31;
    const int i    = sidx[lane];

    for (int c = w; c < OUTC; c += 4) {
        float v;
        if (c < 3) {
            v = xyz[((size_t)b * NP + i) * 3 + c] -
                new_xyz[((size_t)b * NQ + p) * 3 + c];
        } else {
            v = feat[((size_t)b * CF + (c - 3)) * (size_t)NP + i];
        }
        out[(((size_t)b * OUTC + c) * NQ + p) * KS + lane] = v;
    }
}

extern "C" void kernel_launch(void* const* d_in, const int* in_sizes, int n_in,
                              void* d_out, int out_size) {
    const float* xyz     = (const float*)d_in[0];  // (B, N, 3)
    const float* new_xyz = (const float*)d_in[1];  // (B, NPOINT, 3)
    const float* feat    = (const float*)d_in[2];  // (B, C, N)
    float* out = (float*)d_out;                    // (B, 67, NPOINT, 32)

    dim3 g1(NQ / BLK, TPARTS, BQ);
    knn_part_kernel<<<g1, BLK>>>(xyz, new_xyz);

    dim3 g2(NQ, BQ);
    merge_group_kernel<<<g2, 128>>>(xyz, new_xyz, feat, out);
}

// round 2
// speedup vs baseline: 2.4894x; 2.4894x over previous
#include <cuda_runtime.h>

// Problem constants
#define BQ 4          // batch
#define NP 16384      // points
#define NQ 4096       // queries (npoint)
#define CF 64         // feature channels
#define KS 32         // nsample
#define OUTC (CF + 3) // 67 output channels

// Stage-1 tiling
#define TPARTS 4
#define PART (NP / TPARTS)   // 4096 points per partial scan
#define CHUNK 2048           // shared-memory tile of points
#define BLK 128              // threads per block (one query per thread)
#define BUFCAP 16            // per-lane candidate buffer depth

// Scratch: partial top-32 per (b, q, part): 16 MB.  Transposed features: 16 MB.
__device__ float g_pd[(size_t)BQ * NQ * TPARTS * KS];
__device__ int   g_pi[(size_t)BQ * NQ * TPARTS * KS];
__device__ float g_ft[(size_t)BQ * NP * CF];   // (B, N, C)

// Sorted-ascending insert. Strict '<' => stable w.r.t. arrival order => ties
// keep the lower point index first (scan order is ascending index), matching
// jax.lax.top_k's stable tie-breaking.
__device__ __forceinline__ void bubble_insert(float (&bd)[KS], int (&bi)[KS],
                                              float d, int i) {
    if (d < bd[KS - 1]) {
        bd[KS - 1] = d;
        bi[KS - 1] = i;
#pragma unroll
        for (int k = KS - 1; k > 0; --k) {
            if (bd[k] < bd[k - 1]) {
                float td = bd[k]; bd[k] = bd[k - 1]; bd[k - 1] = td;
                int   ti = bi[k]; bi[k] = bi[k - 1]; bi[k - 1] = ti;
            } else {
                break;
            }
        }
    }
}

// ---------------------------------------------------------------------------
// Kernel 0: feature transpose (B, C, N) -> (B, N, C) so the epilogue gather
// reads contiguous 256B rows per neighbor.
// ---------------------------------------------------------------------------
__global__ __launch_bounds__(256)
void transpose_kernel(const float* __restrict__ feat) {
    __shared__ float t[32][33];
    const int b  = blockIdx.z;
    const int n0 = blockIdx.x * 32;
    const int c0 = blockIdx.y * 32;
    const int tx = threadIdx.x;
    const int ty = threadIdx.y;
#pragma unroll
    for (int i = 0; i < 4; i++) {
        const int c = c0 + ty + i * 8;
        t[ty + i * 8][tx] = feat[((size_t)b * CF + c) * NP + n0 + tx];
    }
    __syncthreads();
#pragma unroll
    for (int i = 0; i < 4; i++) {
        const int n = n0 + ty + i * 8;
        g_ft[((size_t)b * NP + n) * CF + c0 + tx] = t[tx][ty + i * 8];
    }
}

// ---------------------------------------------------------------------------
// Kernel 1: partial exact top-32 over a 4096-point slice of N, per query.
// Grid: (NQ/BLK, TPARTS, BQ). One query per thread; top-K in REGISTERS
// (launch_bounds allows 256 regs -> no spills). Candidate buffer is
// conflict-free ([slot*BLK + tid] -> bank == tid).
// ---------------------------------------------------------------------------
__global__ __launch_bounds__(BLK, 2)
void knn_part_kernel(const float* __restrict__ xyz,
                     const float* __restrict__ new_xyz) {
    const int b   = blockIdx.z;
    const int t   = blockIdx.y;
    const int q   = blockIdx.x * BLK + threadIdx.x;
    const int tid = threadIdx.x;

    const float* qp = new_xyz + ((size_t)b * NQ + q) * 3;
    const float qx = qp[0], qy = qp[1], qz = qp[2];

    float bd[KS];
    int   bi[KS];
#pragma unroll
    for (int k = 0; k < KS; k++) {
        bd[k] = __int_as_float(0x7f800000); // +inf
        bi[k] = 0;
    }

    __shared__ float4 s_pts[CHUNK];              // 32 KB
    __shared__ float  sbufd[BUFCAP * BLK];       //  8 KB
    __shared__ int    sbufi[BUFCAP * BLK];       //  8 KB

    int cnt = 0;
    const int base = t * PART;

    for (int c0 = 0; c0 < PART; c0 += CHUNK) {
        __syncthreads();
        for (int j = tid; j < CHUNK; j += BLK) {
            const float* p = xyz + ((size_t)b * NP + base + c0 + j) * 3;
            s_pts[j] = make_float4(p[0], p[1], p[2], 0.0f);
        }
        __syncthreads();

        int jstart = 0;
        if (c0 == 0) {
            // Prime the threshold with the first 32 points (direct inserts).
#pragma unroll 1
            for (int j = 0; j < KS; j++) {
                const float4 p = s_pts[j];
                const float dx = qx - p.x, dy = qy - p.y, dz = qz - p.z;
                bubble_insert(bd, bi, fmaf(dx, dx, fmaf(dy, dy, dz * dz)),
                              base + j);
            }
            jstart = KS;
        }

        for (int j = jstart; j < CHUNK; j += 4) {
#pragma unroll
            for (int u = 0; u < 4; u++) {
                const float4 p = s_pts[j + u];
                const float dx = qx - p.x, dy = qy - p.y, dz = qz - p.z;
                const float d  = fmaf(dx, dx, fmaf(dy, dy, dz * dz));
                if (d < bd[KS - 1]) {
                    sbufd[cnt * BLK + tid] = d;
                    sbufi[cnt * BLK + tid] = base + c0 + j + u;
                    cnt++;
                }
            }
            if (__any_sync(0xffffffffu, cnt > BUFCAP - 4)) {
#pragma unroll 1
                for (int u = 0; u < cnt; u++) {
                    bubble_insert(bd, bi, sbufd[u * BLK + tid],
                                  sbufi[u * BLK + tid]);
                }
                cnt = 0;
            }
        }
    }
#pragma unroll 1
    for (int u = 0; u < cnt; u++) {
        bubble_insert(bd, bi, sbufd[u * BLK + tid], sbufi[u * BLK + tid]);
    }

    const size_t o = (((size_t)b * NQ + q) * TPARTS + t) * KS;
#pragma unroll
    for (int k = 0; k < KS; k++) {
        g_pd[o + k] = bd[k];
        g_pi[o + k] = bi[k];
    }
}

// ---------------------------------------------------------------------------
// Kernel 2: exact 4-way merge of sorted partials -> global top-32, fused with
// gather/center/transpose/concat. One query per block (128 threads).
// Neighbor feature rows are staged through smem: coalesced 256B row reads,
// conflict-free (stride-65) smem reads, coalesced 128B output stores.
// ---------------------------------------------------------------------------
__global__ __launch_bounds__(128)
void merge_group_kernel(const float* __restrict__ xyz,
                        const float* __restrict__ new_xyz,
                        float* __restrict__ out) {
    const int p   = blockIdx.x;
    const int b   = blockIdx.y;
    const int tid = threadIdx.x;

    __shared__ float sd[TPARTS * KS];
    __shared__ int   si[TPARTS * KS];
    __shared__ int   sidx[KS];
    __shared__ float sfeat[KS][65];

    const size_t cbase = (((size_t)b * NQ + p) * TPARTS) * KS;
    sd[tid] = g_pd[cbase + tid];
    si[tid] = g_pi[cbase + tid];
    __syncthreads();

    if (tid == 0) {
        int p0 = 0, p1 = 0, p2 = 0, p3 = 0;
        for (int k = 0; k < KS; k++) {
            float d0 = sd[0 * KS + p0]; int i0 = si[0 * KS + p0];
            float d1 = sd[1 * KS + p1]; int i1 = si[1 * KS + p1];
            float d2 = sd[2 * KS + p2]; int i2 = si[2 * KS + p2];
            float d3 = sd[3 * KS + p3]; int i3 = si[3 * KS + p3];
            float bdv = d0; int biv = i0; int sel = 0;
            if (d1 < bdv || (d1 == bdv && i1 < biv)) { bdv = d1; biv = i1; sel = 1; }
            if (d2 < bdv || (d2 == bdv && i2 < biv)) { bdv = d2; biv = i2; sel = 2; }
            if (d3 < bdv || (d3 == bdv && i3 < biv)) { bdv = d3; biv = i3; sel = 3; }
            sidx[k] = biv;
            if      (sel == 0) p0++;
            else if (sel == 1) p1++;
            else if (sel == 2) p2++;
            else               p3++;
        }
    }
    __syncthreads();

    const int w    = tid >> 5;
    const int lane = tid & 31;

    // Stage neighbor feature rows: warp w loads rows w, w+4, ... (256B each).
    for (int s = w; s < KS; s += 4) {
        const float2* row =
            (const float2*)(g_ft + ((size_t)b * NP + sidx[s]) * CF);
        const float2 v = row[lane];
        sfeat[s][lane * 2]     = v.x;
        sfeat[s][lane * 2 + 1] = v.y;
    }
    __syncthreads();

    const int i = sidx[lane];
    for (int c = w; c < OUTC; c += 4) {
        float v;
        if (c < 3) {
            v = xyz[((size_t)b * NP + i) * 3 + c] -
                new_xyz[((size_t)b * NQ + p) * 3 + c];
        } else {
            v = sfeat[lane][c - 3];
        }
        out[(((size_t)b * OUTC + c) * NQ + p) * KS + lane] = v;
    }
}

extern "C" void kernel_launch(void* const* d_in, const int* in_sizes, int n_in,
                              void* d_out, int out_size) {
    const float* xyz     = (const float*)d_in[0];  // (B, N, 3)
    const float* new_xyz = (const float*)d_in[1];  // (B, NPOINT, 3)
    const float* feat    = (const float*)d_in[2];  // (B, C, N)
    float* out = (float*)d_out;                    // (B, 67, NPOINT, 32)

    dim3 gt(NP / 32, CF / 32, BQ);
    transpose_kernel<<<gt, dim3(32, 8)>>>(feat);

    dim3 g1(NQ / BLK, TPARTS, BQ);
    knn_part_kernel<<<g1, BLK>>>(xyz, new_xyz);

    dim3 g2(NQ, BQ);
    merge_group_kernel<<<g2, 128>>>(xyz, new_xyz, out);
}

// round 3
// speedup vs baseline: 18.7665x; 7.5386x over previous
#include <cuda_runtime.h>

// Problem constants
#define BQ 4          // batch
#define NP 16384      // points
#define NQ 4096       // queries (npoint)
#define CF 64         // feature channels
#define KS 32         // nsample
#define OUTC (CF + 3) // 67 output channels

#define WPB 8         // warps (queries) per block
#define TILE 2048     // shared-memory tile of points

#define FULLM 0xffffffffu
#define INFKEY 0xffffffffffffffffULL

// Scratch: final neighbor indices (2 MB) + transposed features (16 MB).
__device__ int   g_idx[(size_t)BQ * NQ * KS];
__device__ float g_ft[(size_t)BQ * NP * CF];   // (B, N, C)

__device__ __forceinline__ unsigned long long pack_key(float d, int idx) {
    // d >= 0 -> float bits are order-preserving; (dist, idx) lexicographic.
    return ((unsigned long long)__float_as_uint(d) << 32) | (unsigned int)idx;
}

// Warp-wide bitonic sort, ascending, one key per lane.
__device__ __forceinline__ unsigned long long
warp_bitonic_sort(unsigned long long key, int lane) {
#pragma unroll
    for (int k = 2; k <= 32; k <<= 1) {
#pragma unroll
        for (int j = k >> 1; j > 0; j >>= 1) {
            unsigned long long other = __shfl_xor_sync(FULLM, key, j);
            bool take_min = (((lane & k) == 0) == ((lane & j) == 0));
            bool lt = key < other;
            key = (take_min == lt) ? key : other;
        }
    }
    return key;
}

// Keep lowest 32 of (top asc-sorted) U (cand asc-sorted), result asc-sorted.
__device__ __forceinline__ unsigned long long
warp_merge_topk(unsigned long long top, unsigned long long cand, int lane) {
    unsigned long long crev = __shfl_sync(FULLM, cand, 31 - lane);
    unsigned long long v = (top < crev) ? top : crev;   // bitonic, = lowest 32
#pragma unroll
    for (int j = 16; j > 0; j >>= 1) {                  // bitonic cleanup
        unsigned long long other = __shfl_xor_sync(FULLM, v, j);
        bool lower = (lane & j) == 0;
        bool lt = v < other;
        v = (lower == lt) ? v : other;
    }
    return v;
}

// ---------------------------------------------------------------------------
// Kernel 1: exact KNN, one WARP per query. Lanes scan strided points, filter
// against the warp's 32nd-best key, compact survivors into a per-warp smem
// buffer, and fold 32-candidate batches via bitonic sort + top-k merge.
// Writes the final ascending-sorted 32 neighbor indices.
// ---------------------------------------------------------------------------
__global__ __launch_bounds__(WPB * 32)
void knn_kernel(const float* __restrict__ xyz,
                const float* __restrict__ new_xyz) {
    const int b    = blockIdx.y;
    const int warp = threadIdx.x >> 5;
    const int lane = threadIdx.x & 31;
    const int q    = blockIdx.x * WPB + warp;

    const float* qp = new_xyz + ((size_t)b * NQ + q) * 3;
    const float qx = qp[0], qy = qp[1], qz = qp[2];

    __shared__ float4 s_pts[TILE];                       // 32 KB
    __shared__ unsigned long long s_cand[WPB][64];       //  4 KB

    unsigned long long top    = INFKEY;
    unsigned long long thresh = INFKEY;
    int cnt = 0;

    for (int t0 = 0; t0 < NP; t0 += TILE) {
        __syncthreads();
        for (int j = threadIdx.x; j < TILE; j += WPB * 32) {
            const float* p = xyz + ((size_t)b * NP + t0 + j) * 3;
            s_pts[j] = make_float4(p[0], p[1], p[2], 0.0f);
        }
        __syncthreads();

        for (int j = 0; j < TILE; j += 32) {
            const float4 p = s_pts[j + lane];
            const float dx = qx - p.x, dy = qy - p.y, dz = qz - p.z;
            const float d  = fmaf(dx, dx, fmaf(dy, dy, dz * dz));
            const unsigned long long key = pack_key(d, t0 + j + lane);
            const bool pred = key < thresh;
            const unsigned m = __ballot_sync(FULLM, pred);
            if (m) {
                const int pos = cnt + __popc(m & ((1u << lane) - 1u));
                if (pred) s_cand[warp][pos] = key;
                cnt += __popc(m);
                if (cnt >= 32) {
                    unsigned long long c = s_cand[warp][lane];
                    c   = warp_bitonic_sort(c, lane);
                    top = warp_merge_topk(top, c, lane);
                    thresh = __shfl_sync(FULLM, top, 31);
                    const int rem = cnt - 32;
                    unsigned long long mv =
                        (lane < rem) ? s_cand[warp][32 + lane] : 0ULL;
                    __syncwarp(FULLM);
                    if (lane < rem) s_cand[warp][lane] = mv;
                    cnt = rem;
                }
            }
        }
    }
    // Drain remaining candidates (pad to 32 with +inf keys).
    if (cnt > 0) {
        unsigned long long c =
            (lane < cnt) ? s_cand[warp][lane] : INFKEY;
        c   = warp_bitonic_sort(c, lane);
        top = warp_merge_topk(top, c, lane);
    }

    // top is ascending by (dist, idx) -> slot order matches top_k output.
    g_idx[((size_t)b * NQ + q) * KS + lane] = (int)(top & 0xffffffffu);
}

// ---------------------------------------------------------------------------
// Kernel 0: feature transpose (B, C, N) -> (B, N, C).
// ---------------------------------------------------------------------------
__global__ __launch_bounds__(256)
void transpose_kernel(const float* __restrict__ feat) {
    __shared__ float t[32][33];
    const int b  = blockIdx.z;
    const int n0 = blockIdx.x * 32;
    const int c0 = blockIdx.y * 32;
    const int tx = threadIdx.x;
    const int ty = threadIdx.y;
#pragma unroll
    for (int i = 0; i < 4; i++) {
        const int c = c0 + ty + i * 8;
        t[ty + i * 8][tx] = feat[((size_t)b * CF + c) * NP + n0 + tx];
    }
    __syncthreads();
#pragma unroll
    for (int i = 0; i < 4; i++) {
        const int n = n0 + ty + i * 8;
        g_ft[((size_t)b * NP + n) * CF + c0 + tx] = t[tx][ty + i * 8];
    }
}

// ---------------------------------------------------------------------------
// Kernel 2: gather / center / transpose / concat. One query per block.
// Coalesced 256B feature-row reads -> smem -> coalesced 128B output stores.
// ---------------------------------------------------------------------------
__global__ __launch_bounds__(128)
void group_kernel(const float* __restrict__ xyz,
                  const float* __restrict__ new_xyz,
                  float* __restrict__ out) {
    const int p   = blockIdx.x;
    const int b   = blockIdx.y;
    const int tid = threadIdx.x;
    const int w    = tid >> 5;
    const int lane = tid & 31;

    __shared__ int   sidx[KS];
    __shared__ float sfeat[KS][65];

    if (tid < KS) sidx[tid] = g_idx[((size_t)b * NQ + p) * KS + tid];
    __syncthreads();

    // Stage neighbor feature rows: warp w loads rows w, w+4, ... (256B each).
    for (int s = w; s < KS; s += 4) {
        const float2* row =
            (const float2*)(g_ft + ((size_t)b * NP + sidx[s]) * CF);
        const float2 v = row[lane];
        sfeat[s][lane * 2]     = v.x;
        sfeat[s][lane * 2 + 1] = v.y;
    }
    __syncthreads();

    const int i = sidx[lane];
    for (int c = w; c < OUTC; c += 4) {
        float v;
        if (c < 3) {
            v = xyz[((size_t)b * NP + i) * 3 + c] -
                new_xyz[((size_t)b * NQ + p) * 3 + c];
        } else {
            v = sfeat[lane][c - 3];
        }
        out[(((size_t)b * OUTC + c) * NQ + p) * KS + lane] = v;
    }
}

extern "C" void kernel_launch(void* const* d_in, const int* in_sizes, int n_in,
                              void* d_out, int out_size) {
    const float* xyz     = (const float*)d_in[0];  // (B, N, 3)
    const float* new_xyz = (const float*)d_in[1];  // (B, NPOINT, 3)
    const float* feat    = (const float*)d_in[2];  // (B, C, N)
    float* out = (float*)d_out;                    // (B, 67, NPOINT, 32)

    // knn first so ncu's (-s 5 -c 1) capture lands on it.
    dim3 g1(NQ / WPB, BQ);
    knn_kernel<<<g1, WPB * 32>>>(xyz, new_xyz);

    dim3 gt(NP / 32, CF / 32, BQ);
    transpose_kernel<<<gt, dim3(32, 8)>>>(feat);

    dim3 g2(NQ, BQ);
    group_kernel<<<g2, 128>>>(xyz, new_xyz, out);
}